// round 4
// baseline (speedup 1.0000x reference)
#include <cuda_runtime.h>
#include <cstdint>
#include <cstddef>

#define B_ 128
#define N_ 196
#define E_ 2048
#define D_ 512
#define A_ 512
#define M_ (B_*N_)   // 25088

// ---- scratch (no allocations allowed) ----
__device__ float g_c2[B_*A_];     // att2 + bd + be, [B][A]
__device__ float g_sp[M_*16];     // partial scores, 16 slices per row

// ---- helpers ----
__device__ __forceinline__ float f2tf32(float x){
    uint32_t u; asm("cvt.rna.tf32.f32 %0, %1;" : "=r"(u) : "f"(x));
    return __uint_as_float(u);
}
__device__ __forceinline__ void mma8(float&d0,float&d1,float&d2,float&d3,
    uint32_t a0,uint32_t a1,uint32_t a2,uint32_t a3,uint32_t b0,uint32_t b1){
    asm volatile("mma.sync.aligned.m16n8k8.row.col.f32.tf32.tf32.f32 "
        "{%0,%1,%2,%3},{%4,%5,%6,%7},{%8,%9},{%0,%1,%2,%3};\n"
        : "+f"(d0),"+f"(d1),"+f"(d2),"+f"(d3)
        : "r"(a0),"r"(a1),"r"(a2),"r"(a3),"r"(b0),"r"(b1));
}

// ============================================================
// K1: g_c2[b][a] = sum_d dec[b][d]*Wd[d][a] + bd[a] + be[a]
// grid (A/128=4, B/16=8), 256 threads
// ============================================================
__global__ __launch_bounds__(256) void att2_kernel(
    const float* __restrict__ dec, const float* __restrict__ Wd,
    const float* __restrict__ bd,  const float* __restrict__ be)
{
    __shared__ float sDec[16*D_];
    const int tid = threadIdx.x;
    const int a0 = blockIdx.x*128, b0 = blockIdx.y*16;

    const float4* src = (const float4*)(dec + (size_t)b0*D_);
    float4* dst = (float4*)sDec;
    for (int i=tid; i<16*D_/4; i+=256) dst[i] = src[i];
    __syncthreads();

    const int tx = tid & 31, ty = tid >> 5;
    const float4* wp = (const float4*)(Wd + a0) + tx;
    float4 acc0 = {0,0,0,0}, acc1 = {0,0,0,0};
    for (int d=0; d<D_; d++){
        float4 w = wp[(size_t)d*(A_/4)];
        float x0 = sDec[ty*D_ + d];
        float x1 = sDec[(ty+8)*D_ + d];
        acc0.x += w.x*x0; acc0.y += w.y*x0; acc0.z += w.z*x0; acc0.w += w.w*x0;
        acc1.x += w.x*x1; acc1.y += w.y*x1; acc1.z += w.z*x1; acc1.w += w.w*x1;
    }
    const int a = a0 + tx*4;
    float bx = bd[a]   + be[a];
    float by = bd[a+1] + be[a+1];
    float bz = bd[a+2] + be[a+2];
    float bw = bd[a+3] + be[a+3];
    float4 o0 = {acc0.x+bx, acc0.y+by, acc0.z+bz, acc0.w+bw};
    float4 o1 = {acc1.x+bx, acc1.y+by, acc1.z+bz, acc1.w+bw};
    *(float4*)&g_c2[(size_t)(b0+ty  )*A_ + a] = o0;
    *(float4*)&g_c2[(size_t)(b0+ty+8)*A_ + a] = o1;
}

// ============================================================
// K2: fused score GEMM (tf32 mma.sync)
//   acc[m][a] = enc[m,:] @ We[:,a]   (m = b*196+n, K=2048)
//   partial_score = sum_a tanh(acc + g_c2[b][a]) * Wf[a]
// CTA tile 256x64, K-chunk 32, warp tile 64x32 (warps 4x2)
// grid (8 a-chunks, 98 m-tiles), 256 threads
// ============================================================
#define MT 256
#define NT 64
#define KC 32
#define ASTR 36   // 144B rows: 16B aligned, conflict-free (4q+c)
#define BSTR 72   // 288B rows: 16B aligned, conflict-free (8k+n)

__global__ __launch_bounds__(256,1) void score_kernel(
    const float* __restrict__ enc, const float* __restrict__ We,
    const float* __restrict__ Wf)
{
    extern __shared__ float sm[];
    float* sA = sm;                 // 2 * MT*ASTR floats
    float* sB = sm + 2*MT*ASTR;     // 2 * KC*BSTR floats

    const int tid  = threadIdx.x;
    const int lane = tid & 31, warp = tid >> 5;
    const int wm = (warp >> 1) * 64;   // warp m offset (0..192)
    const int wn = (warp & 1) * 32;    // warp n offset (0 or 32)
    const int m0 = blockIdx.y * MT;
    const int a0 = blockIdx.x * NT;

    const int arow = tid >> 3, akv = (tid & 7) * 4;   // A tile load map
    const int brow = tid >> 4, bnv = (tid & 15) * 4;  // B tile load map

    const float* gA = enc + (size_t)m0 * E_;
    const float* gB = We + a0;

    float acc[4][4][4];
    #pragma unroll
    for (int i=0;i<4;i++)
        #pragma unroll
        for (int j=0;j<4;j++)
            #pragma unroll
            for (int k=0;k<4;k++) acc[i][j][k] = 0.f;

    float4 ra[8], rb[2];

    auto loadG = [&](int k0){
        #pragma unroll
        for (int p=0;p<8;p++)
            ra[p] = *(const float4*)(gA + (size_t)(arow + p*32)*E_ + k0 + akv);
        #pragma unroll
        for (int p=0;p<2;p++)
            rb[p] = *(const float4*)(gB + (size_t)(k0 + brow + p*16)*A_ + bnv);
    };
    auto storeS = [&](int buf){
        float* bA = sA + buf*MT*ASTR;
        float* bB = sB + buf*KC*BSTR;
        #pragma unroll
        for (int p=0;p<8;p++){
            float4 v = ra[p];
            v.x=f2tf32(v.x); v.y=f2tf32(v.y); v.z=f2tf32(v.z); v.w=f2tf32(v.w);
            *(float4*)&bA[(arow + p*32)*ASTR + akv] = v;
        }
        #pragma unroll
        for (int p=0;p<2;p++){
            float4 v = rb[p];
            v.x=f2tf32(v.x); v.y=f2tf32(v.y); v.z=f2tf32(v.z); v.w=f2tf32(v.w);
            *(float4*)&bB[(brow + p*16)*BSTR + bnv] = v;
        }
    };

    loadG(0); storeS(0);
    __syncthreads();

    const int q = lane >> 2;      // 0..7
    const int c = lane & 3;       // 0..3

    for (int kc=0; kc<E_/KC; kc++){
        const int cur = kc & 1;
        if (kc < E_/KC - 1) loadG((kc+1)*KC);

        const float* cA = sA + cur*MT*ASTR;
        const float* cB = sB + cur*KC*BSTR;
        #pragma unroll
        for (int kk=0; kk<4; kk++){
            uint32_t af[4][4], bfr[4][2];
            #pragma unroll
            for (int ms=0; ms<4; ms++){
                const float* p = cA + (wm + ms*16 + q)*ASTR + kk*8 + c;
                af[ms][0] = __float_as_uint(p[0]);
                af[ms][1] = __float_as_uint(p[8*ASTR]);
                af[ms][2] = __float_as_uint(p[4]);
                af[ms][3] = __float_as_uint(p[8*ASTR+4]);
            }
            #pragma unroll
            for (int ns=0; ns<4; ns++){
                const float* p = cB + (kk*8 + c)*BSTR + wn + ns*8 + q;
                bfr[ns][0] = __float_as_uint(p[0]);
                bfr[ns][1] = __float_as_uint(p[4*BSTR]);
            }
            #pragma unroll
            for (int ms=0; ms<4; ms++)
                #pragma unroll
                for (int ns=0; ns<4; ns++)
                    mma8(acc[ms][ns][0],acc[ms][ns][1],acc[ms][ns][2],acc[ms][ns][3],
                         af[ms][0],af[ms][1],af[ms][2],af[ms][3],
                         bfr[ns][0],bfr[ns][1]);
            }
        if (kc < E_/KC - 1) storeS(cur ^ 1);
        __syncthreads();
    }

    // ---- epilogue: tanh(+c2) dot Wf, quad-reduce, write partials ----
    const int c2i = c*2;
    #pragma unroll
    for (int ms=0; ms<4; ms++){
        const int r0 = m0 + wm + ms*16 + q;
        const int r1 = r0 + 8;
        const int b0 = r0 / N_;
        const int b1 = r1 / N_;
        float s0 = 0.f, s1 = 0.f;
        #pragma unroll
        for (int ns=0; ns<4; ns++){
            const int ag = a0 + wn + ns*8 + c2i;
            const float w0 = __ldg(&Wf[ag]), w1 = __ldg(&Wf[ag+1]);
            const float c00 = g_c2[(size_t)b0*A_ + ag], c01 = g_c2[(size_t)b0*A_ + ag + 1];
            const float c10 = g_c2[(size_t)b1*A_ + ag], c11 = g_c2[(size_t)b1*A_ + ag + 1];
            s0 += tanhf(acc[ms][ns][0] + c00) * w0 + tanhf(acc[ms][ns][1] + c01) * w1;
            s1 += tanhf(acc[ms][ns][2] + c10) * w0 + tanhf(acc[ms][ns][3] + c11) * w1;
        }
        s0 += __shfl_xor_sync(0xffffffffu, s0, 1);
        s0 += __shfl_xor_sync(0xffffffffu, s0, 2);
        s1 += __shfl_xor_sync(0xffffffffu, s1, 1);
        s1 += __shfl_xor_sync(0xffffffffu, s1, 2);
        if (c == 0){
            g_sp[(size_t)r0*16 + blockIdx.x*2 + (warp & 1)] = s0;
            g_sp[(size_t)r1*16 + blockIdx.x*2 + (warp & 1)] = s1;
        }
    }
}

// ============================================================
// K3: softmax over n per batch (bf offset cancels, dropped)
// grid 128, 256 threads
// ============================================================
__global__ __launch_bounds__(256) void softmax_kernel(float* __restrict__ alpha)
{
    __shared__ float sh[256];
    const int b = blockIdx.x, t = threadIdx.x;
    float val = 0.f;
    if (t < N_){
        const float* p = &g_sp[(size_t)(b*N_ + t)*16];
        #pragma unroll
        for (int j=0;j<16;j++) val += p[j];
    }
    sh[t] = (t < N_) ? val : -1e30f;
    __syncthreads();
    for (int s=128; s>0; s>>=1){
        if (t < s) sh[t] = fmaxf(sh[t], sh[t+s]);
        __syncthreads();
    }
    const float mx = sh[0];
    __syncthreads();
    const float e = (t < N_) ? expf(val - mx) : 0.f;
    sh[t] = e;
    __syncthreads();
    for (int s=128; s>0; s>>=1){
        if (t < s) sh[t] += sh[t+s];
        __syncthreads();
    }
    const float inv = 1.f / sh[0];
    if (t < N_) alpha[(size_t)b*N_ + t] = e * inv;
}

// ============================================================
// K4: context[b][e] = sum_n alpha[b][n] * enc[b][n][e]
// grid (E/512=4, B=128), 128 threads (float4 per thread)
// ============================================================
__global__ __launch_bounds__(128) void ctx_kernel(
    const float* __restrict__ enc, const float* __restrict__ alpha,
    float* __restrict__ out)
{
    __shared__ float sal[N_];
    const int b = blockIdx.y;
    const int t = threadIdx.x;
    for (int i=t; i<N_; i+=128) sal[i] = alpha[(size_t)b*N_ + i];
    __syncthreads();

    const float4* pe = (const float4*)(enc + (size_t)b*N_*E_ + blockIdx.x*512) + t;
    float4 acc = {0,0,0,0};
    #pragma unroll 4
    for (int n=0; n<N_; n++){
        const float a = sal[n];
        const float4 v = pe[(size_t)n*(E_/4)];
        acc.x += v.x*a; acc.y += v.y*a; acc.z += v.z*a; acc.w += v.w*a;
    }
    ((float4*)(out + (size_t)b*E_ + blockIdx.x*512))[t] = acc;
}

// ============================================================
extern "C" void kernel_launch(void* const* d_in, const int* in_sizes, int n_in,
                              void* d_out, int out_size)
{
    (void)in_sizes; (void)n_in; (void)out_size;
    const float* enc = (const float*)d_in[0];   // (B,N,E)
    const float* dec = (const float*)d_in[1];   // (B,D)
    const float* We  = (const float*)d_in[2];   // (E,A)
    const float* be  = (const float*)d_in[3];   // (A)
    const float* Wd  = (const float*)d_in[4];   // (D,A)
    const float* bd  = (const float*)d_in[5];   // (A)
    const float* Wf  = (const float*)d_in[6];   // (A,1)
    // d_in[7] = bf : constant shift, softmax-invariant -> unused

    float* ctx_out   = (float*)d_out;                  // (B,E)
    float* alpha_out = ctx_out + (size_t)B_*E_;        // (B,N,1)

    const size_t SMEM = (size_t)(2*MT*ASTR + 2*KC*BSTR) * sizeof(float); // 92160
    cudaFuncSetAttribute(score_kernel, cudaFuncAttributeMaxDynamicSharedMemorySize, (int)SMEM);

    att2_kernel<<<dim3(4,8), 256>>>(dec, Wd, bd, be);
    score_kernel<<<dim3(8,98), 256, SMEM>>>(enc, We, Wf);
    softmax_kernel<<<128, 256>>>(alpha_out);
    ctx_kernel<<<dim3(4,128), 128>>>(enc, alpha_out, ctx_out);
}

// round 6
// speedup vs baseline: 1.1206x; 1.1206x over previous
#include <cuda_runtime.h>
#include <cstdint>
#include <cstddef>

#define B_ 128
#define N_ 196
#define E_ 2048
#define D_ 512
#define A_ 512
#define M_ (B_*N_)   // 25088

// ---- device scratch (allocation-free rule) ----
__device__ float g_c2[B_*A_];     // att2 + bd + be, [B][A]
__device__ float g_sp[M_*16];     // partial scores, 16 slices per row

// ---- helpers ----
__device__ __forceinline__ float f2tf32(float x){
    uint32_t u; asm("cvt.rna.tf32.f32 %0, %1;" : "=r"(u) : "f"(x));
    return __uint_as_float(u);
}
__device__ __forceinline__ void mma8(float&d0,float&d1,float&d2,float&d3,
    uint32_t a0,uint32_t a1,uint32_t a2,uint32_t a3,uint32_t b0,uint32_t b1){
    asm volatile("mma.sync.aligned.m16n8k8.row.col.f32.tf32.tf32.f32 "
        "{%0,%1,%2,%3},{%4,%5,%6,%7},{%8,%9},{%0,%1,%2,%3};\n"
        : "+f"(d0),"+f"(d1),"+f"(d2),"+f"(d3)
        : "r"(a0),"r"(a1),"r"(a2),"r"(a3),"r"(b0),"r"(b1));
}

// ============================================================
// K1: g_c2[b][a] = dec[b]@Wd[:,a] + bd[a] + be[a]
// grid (4,8), 256 threads
// ============================================================
__global__ __launch_bounds__(256) void att2_kernel(
    const float* __restrict__ dec, const float* __restrict__ Wd,
    const float* __restrict__ bd,  const float* __restrict__ be)
{
    __shared__ float sDec[16*D_];
    const int tid = threadIdx.x;
    const int a0 = blockIdx.x*128, b0 = blockIdx.y*16;

    const float4* src = (const float4*)(dec + (size_t)b0*D_);
    float4* dst = (float4*)sDec;
    for (int i=tid; i<16*D_/4; i+=256) dst[i] = src[i];
    __syncthreads();

    const int tx = tid & 31, ty = tid >> 5;
    const float4* wp = (const float4*)(Wd + a0) + tx;
    float4 acc0 = {0,0,0,0}, acc1 = {0,0,0,0};
    for (int d=0; d<D_; d++){
        float4 w = wp[(size_t)d*(A_/4)];
        float x0 = sDec[ty*D_ + d];
        float x1 = sDec[(ty+8)*D_ + d];
        acc0.x += w.x*x0; acc0.y += w.y*x0; acc0.z += w.z*x0; acc0.w += w.w*x0;
        acc1.x += w.x*x1; acc1.y += w.y*x1; acc1.z += w.z*x1; acc1.w += w.w*x1;
    }
    const int a = a0 + tx*4;
    float bx = bd[a]   + be[a];
    float by = bd[a+1] + be[a+1];
    float bz = bd[a+2] + be[a+2];
    float bw = bd[a+3] + be[a+3];
    float4 o0 = {acc0.x+bx, acc0.y+by, acc0.z+bz, acc0.w+bw};
    float4 o1 = {acc1.x+bx, acc1.y+by, acc1.z+bz, acc1.w+bw};
    *(float4*)&g_c2[(size_t)(b0+ty  )*A_ + a] = o0;
    *(float4*)&g_c2[(size_t)(b0+ty+8)*A_ + a] = o1;
}

// ============================================================
// K2: fused score GEMM (tf32 mma.sync), occupancy-2 version
//   CTA tile 128x64, K-chunk 32, warps 4m x 2n, warp tile 32x32
//   grid (8 a-chunks, 196 m-tiles), 256 threads, 2 CTAs/SM
// ============================================================
#define MT 128
#define NT 64
#define KC 32
#define ASTR 36   // A: [m][k] rows of 32 floats, stride 36 (conflict-free)
#define BSTR 72   // B: [k][n] rows of 64 floats, stride 72 (conflict-free)
#define SMEM_K2 ((2*MT*ASTR + 2*KC*BSTR)*4)   // 55296 B

__global__ __launch_bounds__(256,2) void score_kernel(
    const float* __restrict__ enc, const float* __restrict__ We,
    const float* __restrict__ Wf)
{
    extern __shared__ float sm[];
    float* sA = sm;                 // 2 * MT*ASTR
    float* sB = sm + 2*MT*ASTR;     // 2 * KC*BSTR

    const int tid  = threadIdx.x;
    const int lane = tid & 31, warp = tid >> 5;
    const int wm = (warp >> 1) * 32;   // warp m offset (0,32,64,96)
    const int wn = (warp & 1) * 32;    // warp n offset (0 or 32)
    const int m0 = blockIdx.y * MT;
    const int a0 = blockIdx.x * NT;

    const int arow = tid >> 3, akv = (tid & 7) * 4;   // A: 32 rows/pass, 4 passes
    const int brow = tid >> 4, bnv = (tid & 15) * 4;  // B: 16 k-rows/pass, 2 passes

    const float* gA = enc + (size_t)m0 * E_;
    const float* gB = We + a0;

    float acc[2][4][4];
    #pragma unroll
    for (int i=0;i<2;i++)
        #pragma unroll
        for (int j=0;j<4;j++)
            #pragma unroll
            for (int k=0;k<4;k++) acc[i][j][k] = 0.f;

    float4 ra[4], rb[2];

    auto loadG = [&](int k0){
        #pragma unroll
        for (int p=0;p<4;p++)
            ra[p] = *(const float4*)(gA + (size_t)(arow + p*32)*E_ + k0 + akv);
        #pragma unroll
        for (int p=0;p<2;p++)
            rb[p] = *(const float4*)(gB + (size_t)(k0 + brow + p*16)*A_ + bnv);
    };
    auto storeS = [&](int buf){
        float* bA = sA + buf*MT*ASTR;
        float* bB = sB + buf*KC*BSTR;
        #pragma unroll
        for (int p=0;p<4;p++){
            float4 v = ra[p];
            v.x=f2tf32(v.x); v.y=f2tf32(v.y); v.z=f2tf32(v.z); v.w=f2tf32(v.w);
            *(float4*)&bA[(arow + p*32)*ASTR + akv] = v;
        }
        #pragma unroll
        for (int p=0;p<2;p++){
            float4 v = rb[p];
            v.x=f2tf32(v.x); v.y=f2tf32(v.y); v.z=f2tf32(v.z); v.w=f2tf32(v.w);
            *(float4*)&bB[(brow + p*16)*BSTR + bnv] = v;
        }
    };

    loadG(0); storeS(0);
    __syncthreads();

    const int q = lane >> 2;      // 0..7
    const int c = lane & 3;       // 0..3

    for (int kc=0; kc<E_/KC; kc++){
        const int cur = kc & 1;
        if (kc < E_/KC - 1) loadG((kc+1)*KC);

        const float* cA = sA + cur*MT*ASTR;
        const float* cB = sB + cur*KC*BSTR;
        #pragma unroll
        for (int kk=0; kk<4; kk++){
            uint32_t af[2][4], bfr[4][2];
            #pragma unroll
            for (int ms=0; ms<2; ms++){
                const float* p = cA + (wm + ms*16 + q)*ASTR + kk*8 + c;
                af[ms][0] = __float_as_uint(p[0]);
                af[ms][1] = __float_as_uint(p[8*ASTR]);
                af[ms][2] = __float_as_uint(p[4]);
                af[ms][3] = __float_as_uint(p[8*ASTR+4]);
            }
            #pragma unroll
            for (int ns=0; ns<4; ns++){
                const float* p = cB + (kk*8 + c)*BSTR + wn + ns*8 + q;
                bfr[ns][0] = __float_as_uint(p[0]);
                bfr[ns][1] = __float_as_uint(p[4*BSTR]);
            }
            #pragma unroll
            for (int ms=0; ms<2; ms++)
                #pragma unroll
                for (int ns=0; ns<4; ns++)
                    mma8(acc[ms][ns][0],acc[ms][ns][1],acc[ms][ns][2],acc[ms][ns][3],
                         af[ms][0],af[ms][1],af[ms][2],af[ms][3],
                         bfr[ns][0],bfr[ns][1]);
        }
        if (kc < E_/KC - 1) storeS(cur ^ 1);
        __syncthreads();
    }

    // ---- epilogue: tanh(+c2) dot Wf, quad-reduce, write partials ----
    const int c2i = c*2;
    #pragma unroll
    for (int ms=0; ms<2; ms++){
        const int r0 = m0 + wm + ms*16 + q;
        const int r1 = r0 + 8;
        const int b0 = r0 / N_;
        const int b1 = r1 / N_;
        float s0 = 0.f, s1 = 0.f;
        #pragma unroll
        for (int ns=0; ns<4; ns++){
            const int ag = a0 + wn + ns*8 + c2i;
            const float w0 = __ldg(&Wf[ag]), w1 = __ldg(&Wf[ag+1]);
            const float c00 = g_c2[(size_t)b0*A_ + ag], c01 = g_c2[(size_t)b0*A_ + ag + 1];
            const float c10 = g_c2[(size_t)b1*A_ + ag], c11 = g_c2[(size_t)b1*A_ + ag + 1];
            s0 += tanhf(acc[ms][ns][0] + c00) * w0 + tanhf(acc[ms][ns][1] + c01) * w1;
            s1 += tanhf(acc[ms][ns][2] + c10) * w0 + tanhf(acc[ms][ns][3] + c11) * w1;
        }
        s0 += __shfl_xor_sync(0xffffffffu, s0, 1);
        s0 += __shfl_xor_sync(0xffffffffu, s0, 2);
        s1 += __shfl_xor_sync(0xffffffffu, s1, 1);
        s1 += __shfl_xor_sync(0xffffffffu, s1, 2);
        if (c == 0){
            g_sp[(size_t)r0*16 + blockIdx.x*2 + (warp & 1)] = s0;
            g_sp[(size_t)r1*16 + blockIdx.x*2 + (warp & 1)] = s1;
        }
    }
}

// ============================================================
// K3: softmax over n per batch (bf offset cancels, dropped)
// ============================================================
__global__ __launch_bounds__(256) void softmax_kernel(float* __restrict__ alpha)
{
    __shared__ float sh[256];
    const int b = blockIdx.x, t = threadIdx.x;
    float val = 0.f;
    if (t < N_){
        const float* p = &g_sp[(size_t)(b*N_ + t)*16];
        #pragma unroll
        for (int j=0;j<16;j++) val += p[j];
    }
    sh[t] = (t < N_) ? val : -1e30f;
    __syncthreads();
    for (int s=128; s>0; s>>=1){
        if (t < s) sh[t] = fmaxf(sh[t], sh[t+s]);
        __syncthreads();
    }
    const float mx = sh[0];
    __syncthreads();
    const float e = (t < N_) ? expf(val - mx) : 0.f;
    sh[t] = e;
    __syncthreads();
    for (int s=128; s>0; s>>=1){
        if (t < s) sh[t] += sh[t+s];
        __syncthreads();
    }
    const float inv = 1.f / sh[0];
    if (t < N_) alpha[(size_t)b*N_ + t] = e * inv;
}

// ============================================================
// K4: context[b][e] = sum_n alpha[b][n]*enc[b][n][e]
// block 256: two n-halves in parallel + smem combine
// ============================================================
__global__ __launch_bounds__(256) void ctx_kernel(
    const float* __restrict__ enc, const float* __restrict__ alpha,
    float* __restrict__ out)
{
    __shared__ float sal[N_];
    __shared__ float4 sred[128];
    const int b = blockIdx.y;
    const int t = threadIdx.x;
    for (int i=t; i<N_; i+=256) sal[i] = alpha[(size_t)b*N_ + i];
    __syncthreads();

    const int col = t & 127;       // float4 column within 512-wide chunk
    const int nh  = t >> 7;        // n-half
    const float4* pe = (const float4*)(enc + (size_t)b*N_*E_ + blockIdx.x*512) + col;
    const int n0 = nh * 98, n1 = n0 + 98;
    float4 acc = {0,0,0,0};
    #pragma unroll 7
    for (int n=n0; n<n1; n++){
        const float a = sal[n];
        const float4 v = pe[(size_t)n*(E_/4)];
        acc.x += v.x*a; acc.y += v.y*a; acc.z += v.z*a; acc.w += v.w*a;
    }
    if (nh == 1) sred[col] = acc;
    __syncthreads();
    if (nh == 0){
        const float4 o = sred[col];
        acc.x += o.x; acc.y += o.y; acc.z += o.z; acc.w += o.w;
        ((float4*)(out + (size_t)b*E_ + blockIdx.x*512))[col] = acc;
    }
}

// ============================================================
extern "C" void kernel_launch(void* const* d_in, const int* in_sizes, int n_in,
                              void* d_out, int out_size)
{
    (void)in_sizes; (void)n_in; (void)out_size;
    const float* enc = (const float*)d_in[0];   // (B,N,E)
    const float* dec = (const float*)d_in[1];   // (B,D)
    const float* We  = (const float*)d_in[2];   // (E,A)
    const float* be  = (const float*)d_in[3];   // (A)
    const float* Wd  = (const float*)d_in[4];   // (D,A)
    const float* bd  = (const float*)d_in[5];   // (A)
    const float* Wf  = (const float*)d_in[6];   // (A,1)
    // d_in[7] = bf : softmax-invariant, unused

    float* ctx_out   = (float*)d_out;               // (B,E)
    float* alpha_out = ctx_out + (size_t)B_*E_;     // (B,N,1)

    cudaFuncSetAttribute(score_kernel, cudaFuncAttributeMaxDynamicSharedMemorySize, SMEM_K2);

    att2_kernel<<<dim3(4,8), 256>>>(dec, Wd, bd, be);
    score_kernel<<<dim3(8,196), 256, SMEM_K2>>>(enc, We, Wf);
    softmax_kernel<<<128, 256>>>(alpha_out);
    ctx_kernel<<<dim3(4,128), 256>>>(enc, alpha_out, ctx_out);
}

// round 7
// speedup vs baseline: 1.3622x; 1.2155x over previous
#include <cuda_runtime.h>
#include <cstdint>
#include <cstddef>

#define B_ 128
#define N_ 196
#define E_ 2048
#define D_ 512
#define A_ 512
#define M_ (B_*N_)   // 25088

// ---- device scratch (allocation-free rule) ----
__device__ float g_c2[B_*A_];     // att2 + bd + be, [B][A]
__device__ float g_sp[M_*8];      // partial scores, 8 slices per row

// ---- helpers ----
__device__ __forceinline__ void mma8(float&d0,float&d1,float&d2,float&d3,
    uint32_t a0,uint32_t a1,uint32_t a2,uint32_t a3,uint32_t b0,uint32_t b1){
    asm volatile("mma.sync.aligned.m16n8k8.row.col.f32.tf32.tf32.f32 "
        "{%0,%1,%2,%3},{%4,%5,%6,%7},{%8,%9},{%0,%1,%2,%3};\n"
        : "+f"(d0),"+f"(d1),"+f"(d2),"+f"(d3)
        : "r"(a0),"r"(a1),"r"(a2),"r"(a3),"r"(b0),"r"(b1));
}
__device__ __forceinline__ uint32_t smem_u32(const void* p){
    uint32_t a;
    asm("{ .reg .u64 t; cvta.to.shared.u64 t, %1; cvt.u32.u64 %0, t; }" : "=r"(a) : "l"(p));
    return a;
}
__device__ __forceinline__ void cpasync16(uint32_t dst, const void* src){
    asm volatile("cp.async.cg.shared.global [%0], [%1], 16;" :: "r"(dst), "l"(src));
}
#define CP_COMMIT() asm volatile("cp.async.commit_group;" ::: "memory")
#define CP_WAIT1()  asm volatile("cp.async.wait_group 1;" ::: "memory")
#define CP_WAIT0()  asm volatile("cp.async.wait_group 0;" ::: "memory")

// ============================================================
// K1: g_c2[b][a] = dec[b]@Wd[:,a] + bd[a] + be[a]
// ============================================================
__global__ __launch_bounds__(256) void att2_kernel(
    const float* __restrict__ dec, const float* __restrict__ Wd,
    const float* __restrict__ bd,  const float* __restrict__ be)
{
    __shared__ float sDec[16*D_];
    const int tid = threadIdx.x;
    const int a0 = blockIdx.x*128, b0 = blockIdx.y*16;

    const float4* src = (const float4*)(dec + (size_t)b0*D_);
    float4* dst = (float4*)sDec;
    for (int i=tid; i<16*D_/4; i+=256) dst[i] = src[i];
    __syncthreads();

    const int tx = tid & 31, ty = tid >> 5;
    const float4* wp = (const float4*)(Wd + a0) + tx;
    float4 acc0 = {0,0,0,0}, acc1 = {0,0,0,0};
    for (int d=0; d<D_; d++){
        float4 w = wp[(size_t)d*(A_/4)];
        float x0 = sDec[ty*D_ + d];
        float x1 = sDec[(ty+8)*D_ + d];
        acc0.x += w.x*x0; acc0.y += w.y*x0; acc0.z += w.z*x0; acc0.w += w.w*x0;
        acc1.x += w.x*x1; acc1.y += w.y*x1; acc1.z += w.z*x1; acc1.w += w.w*x1;
    }
    const int a = a0 + tx*4;
    float bx = bd[a]   + be[a];
    float by = bd[a+1] + be[a+1];
    float bz = bd[a+2] + be[a+2];
    float bw = bd[a+3] + be[a+3];
    float4 o0 = {acc0.x+bx, acc0.y+by, acc0.z+bz, acc0.w+bw};
    float4 o1 = {acc1.x+bx, acc1.y+by, acc1.z+bz, acc1.w+bw};
    *(float4*)&g_c2[(size_t)(b0+ty  )*A_ + a] = o0;
    *(float4*)&g_c2[(size_t)(b0+ty+8)*A_ + a] = o1;
}

// ============================================================
// K2: fused score GEMM (tf32 mma.sync), cp.async 3-stage
//   CTA tile 128x128, warps 4m x 2n, warp tile 32x64
//   grid (4 a-chunks, 196 m-tiles), 256 threads, 2 CTAs/SM
// ============================================================
#define MT 128
#define NT 128
#define KC 32
#define ASTR 36        // (4q+c) conflict-free, 16B aligned
#define BSTR 136       // (8c+q) conflict-free, 16B aligned
#define ASTG (MT*ASTR) // 4608 floats
#define BSTG (KC*BSTR) // 4352 floats
#define STG  (ASTG+BSTG)          // 8960 floats per stage
#define SMEM_K2 (3*STG*4)         // 107520 B
#define NCH (E_/KC)               // 64

__global__ __launch_bounds__(256,2) void score_kernel(
    const float* __restrict__ enc, const float* __restrict__ We,
    const float* __restrict__ Wf)
{
    extern __shared__ float sm[];
    const uint32_t sbase = smem_u32(sm);

    const int tid  = threadIdx.x;
    const int lane = tid & 31, warp = tid >> 5;
    const int wm = (warp >> 1) * 32;   // warp m offset (0,32,64,96)
    const int wn = (warp & 1) * 64;    // warp n offset (0 or 64)
    const int m0 = blockIdx.y * MT;
    const int a0 = blockIdx.x * NT;

    // cp.async maps: 4 chunks each for A and B per thread
    const int ar = tid >> 3,  ak = (tid & 7) * 4;    // A: row 0..31 (+32p), k-float
    const int bk = tid >> 5,  bn = (tid & 31) * 4;   // B: krow 0..7 (+8p), n-float
    const float* gA = enc + (size_t)(m0 + ar)*E_ + ak;
    const float* gB = We  + (size_t)bk*A_ + a0 + bn;
    const uint32_t dA = sbase + (ar*ASTR + ak)*4;
    const uint32_t dB = sbase + (ASTG + bk*BSTR + bn)*4;

    auto issue = [&](int c){
        const int s = c % 3;
        const uint32_t so = s*STG*4;
        const float* pa = gA + c*KC;
        #pragma unroll
        for (int p=0;p<4;p++)
            cpasync16(so + dA + p*32*ASTR*4, pa + (size_t)p*32*E_);
        const float* pb = gB + (size_t)c*KC*A_;
        #pragma unroll
        for (int p=0;p<4;p++)
            cpasync16(so + dB + p*8*BSTR*4, pb + (size_t)p*8*A_);
        CP_COMMIT();
    };

    float acc[2][8][4];
    #pragma unroll
    for (int i=0;i<2;i++)
        #pragma unroll
        for (int j=0;j<8;j++)
            #pragma unroll
            for (int k=0;k<4;k++) acc[i][j][k] = 0.f;

    issue(0); issue(1);

    const int q = lane >> 2;      // 0..7
    const int c = lane & 3;       // 0..3

    for (int kc=0; kc<NCH; kc++){
        if (kc < NCH-2) { CP_WAIT1(); } else { CP_WAIT0(); }
        __syncthreads();

        const float* cA = sm + (kc%3)*STG;
        const float* cB = cA + ASTG;
        #pragma unroll
        for (int kk=0; kk<4; kk++){
            uint32_t af[2][4], bfr[8][2];
            #pragma unroll
            for (int ms=0; ms<2; ms++){
                const float* p = cA + (wm + ms*16 + q)*ASTR + kk*8 + c;
                af[ms][0] = __float_as_uint(p[0]);
                af[ms][1] = __float_as_uint(p[8*ASTR]);
                af[ms][2] = __float_as_uint(p[4]);
                af[ms][3] = __float_as_uint(p[8*ASTR+4]);
            }
            #pragma unroll
            for (int ns=0; ns<8; ns++){
                const float* p = cB + (kk*8 + c)*BSTR + wn + ns*8 + q;
                bfr[ns][0] = __float_as_uint(p[0]);
                bfr[ns][1] = __float_as_uint(p[4*BSTR]);
            }
            #pragma unroll
            for (int ms=0; ms<2; ms++)
                #pragma unroll
                for (int ns=0; ns<8; ns++)
                    mma8(acc[ms][ns][0],acc[ms][ns][1],acc[ms][ns][2],acc[ms][ns][3],
                         af[ms][0],af[ms][1],af[ms][2],af[ms][3],
                         bfr[ns][0],bfr[ns][1]);
        }
        __syncthreads();
        if (kc < NCH-2) issue(kc+2);
    }

    // ---- epilogue: tanh(+c2) dot Wf, quad-reduce, write partials ----
    const int c2i = c*2;
    #pragma unroll
    for (int ms=0; ms<2; ms++){
        const int r0 = m0 + wm + ms*16 + q;
        const int r1 = r0 + 8;
        const int b0 = r0 / N_;
        const int b1 = r1 / N_;
        float s0 = 0.f, s1 = 0.f;
        #pragma unroll
        for (int ns=0; ns<8; ns++){
            const int ag = a0 + wn + ns*8 + c2i;
            const float w0 = __ldg(&Wf[ag]), w1 = __ldg(&Wf[ag+1]);
            const float c00 = g_c2[(size_t)b0*A_ + ag], c01 = g_c2[(size_t)b0*A_ + ag + 1];
            const float c10 = g_c2[(size_t)b1*A_ + ag], c11 = g_c2[(size_t)b1*A_ + ag + 1];
            s0 += tanhf(acc[ms][ns][0] + c00) * w0 + tanhf(acc[ms][ns][1] + c01) * w1;
            s1 += tanhf(acc[ms][ns][2] + c10) * w0 + tanhf(acc[ms][ns][3] + c11) * w1;
        }
        s0 += __shfl_xor_sync(0xffffffffu, s0, 1);
        s0 += __shfl_xor_sync(0xffffffffu, s0, 2);
        s1 += __shfl_xor_sync(0xffffffffu, s1, 1);
        s1 += __shfl_xor_sync(0xffffffffu, s1, 2);
        if (c == 0){
            g_sp[(size_t)r0*8 + blockIdx.x*2 + (warp & 1)] = s0;
            g_sp[(size_t)r1*8 + blockIdx.x*2 + (warp & 1)] = s1;
        }
    }
}

// ============================================================
// K3: softmax over n per batch (bf offset cancels, dropped)
// ============================================================
__global__ __launch_bounds__(256) void softmax_kernel(float* __restrict__ alpha)
{
    __shared__ float sh[256];
    const int b = blockIdx.x, t = threadIdx.x;
    float val = 0.f;
    if (t < N_){
        const float* p = &g_sp[(size_t)(b*N_ + t)*8];
        #pragma unroll
        for (int j=0;j<8;j++) val += p[j];
    }
    sh[t] = (t < N_) ? val : -1e30f;
    __syncthreads();
    for (int s=128; s>0; s>>=1){
        if (t < s) sh[t] = fmaxf(sh[t], sh[t+s]);
        __syncthreads();
    }
    const float mx = sh[0];
    __syncthreads();
    const float e = (t < N_) ? expf(val - mx) : 0.f;
    sh[t] = e;
    __syncthreads();
    for (int s=128; s>0; s>>=1){
        if (t < s) sh[t] += sh[t+s];
        __syncthreads();
    }
    const float inv = 1.f / sh[0];
    if (t < N_) alpha[(size_t)b*N_ + t] = e * inv;
}

// ============================================================
// K4: context[b][e] = sum_n alpha[b][n]*enc[b][n][e]
// block 512: 4-way n-split + smem combine
// ============================================================
__global__ __launch_bounds__(512) void ctx_kernel(
    const float* __restrict__ enc, const float* __restrict__ alpha,
    float* __restrict__ out)
{
    __shared__ float sal[N_];
    __shared__ float4 sred[3][128];
    const int b = blockIdx.y;
    const int t = threadIdx.x;
    for (int i=t; i<N_; i+=512) sal[i] = alpha[(size_t)b*N_ + i];
    __syncthreads();

    const int col = t & 127;       // float4 column within 512-wide chunk
    const int nq  = t >> 7;        // n-quarter 0..3
    const float4* pe = (const float4*)(enc + (size_t)b*N_*E_ + blockIdx.x*512) + col;
    const int n0 = nq * 49, n1 = n0 + 49;
    float4 acc = {0,0,0,0};
    #pragma unroll 7
    for (int n=n0; n<n1; n++){
        const float a = sal[n];
        const float4 v = pe[(size_t)n*(E_/4)];
        acc.x += v.x*a; acc.y += v.y*a; acc.z += v.z*a; acc.w += v.w*a;
    }
    if (nq > 0) sred[nq-1][col] = acc;
    __syncthreads();
    if (nq == 0){
        #pragma unroll
        for (int j=0;j<3;j++){
            const float4 o = sred[j][col];
            acc.x += o.x; acc.y += o.y; acc.z += o.z; acc.w += o.w;
        }
        ((float4*)(out + (size_t)b*E_ + blockIdx.x*512))[col] = acc;
    }
}

// ============================================================
extern "C" void kernel_launch(void* const* d_in, const int* in_sizes, int n_in,
                              void* d_out, int out_size)
{
    (void)in_sizes; (void)n_in; (void)out_size;
    const float* enc = (const float*)d_in[0];   // (B,N,E)
    const float* dec = (const float*)d_in[1];   // (B,D)
    const float* We  = (const float*)d_in[2];   // (E,A)
    const float* be  = (const float*)d_in[3];   // (A)
    const float* Wd  = (const float*)d_in[4];   // (D,A)
    const float* bd  = (const float*)d_in[5];   // (A)
    const float* Wf  = (const float*)d_in[6];   // (A,1)
    // d_in[7] = bf : softmax-invariant, unused

    float* ctx_out   = (float*)d_out;               // (B,E)
    float* alpha_out = ctx_out + (size_t)B_*E_;     // (B,N,1)

    cudaFuncSetAttribute(score_kernel, cudaFuncAttributeMaxDynamicSharedMemorySize, SMEM_K2);

    att2_kernel<<<dim3(4,8), 256>>>(dec, Wd, bd, be);
    score_kernel<<<dim3(4,196), 256, SMEM_K2>>>(enc, We, Wf);
    softmax_kernel<<<128, 256>>>(alpha_out);
    ctx_kernel<<<dim3(4,128), 512>>>(enc, alpha_out, ctx_out);
}

// round 8
// speedup vs baseline: 1.6996x; 1.2477x over previous
#include <cuda_runtime.h>
#include <cstdint>
#include <cstddef>

#define B_ 128
#define N_ 196
#define E_ 2048
#define D_ 512
#define A_ 512
#define M_ (B_*N_)   // 25088

// ---- device scratch (allocation-free rule) ----
__device__ float g_c2[B_*A_];         // att2 + bd + be, [B][A]
__device__ float g_sp[M_*8];          // partial scores, 8 slices per row
__device__ uint32_t g_Wp[A_*(E_/2)]; // We packed: [n][k/2] fp16x2 (low=even k)

// ---- helpers ----
__device__ __forceinline__ uint32_t pack2(float lo, float hi){
    uint32_t r; asm("cvt.rn.f16x2.f32 %0, %1, %2;" : "=r"(r) : "f"(hi), "f"(lo));
    return r;
}
__device__ __forceinline__ void mma16(float&d0,float&d1,float&d2,float&d3,
    uint32_t a0,uint32_t a1,uint32_t a2,uint32_t a3,uint32_t b0,uint32_t b1){
    asm volatile("mma.sync.aligned.m16n8k16.row.col.f32.f16.f16.f32 "
        "{%0,%1,%2,%3},{%4,%5,%6,%7},{%8,%9},{%0,%1,%2,%3};\n"
        : "+f"(d0),"+f"(d1),"+f"(d2),"+f"(d3)
        : "r"(a0),"r"(a1),"r"(a2),"r"(a3),"r"(b0),"r"(b1));
}
__device__ __forceinline__ uint32_t smem_u32(const void* p){
    uint32_t a;
    asm("{ .reg .u64 t; cvta.to.shared.u64 t, %1; cvt.u32.u64 %0, t; }" : "=r"(a) : "l"(p));
    return a;
}
__device__ __forceinline__ void cpasync16(uint32_t dst, const void* src){
    asm volatile("cp.async.cg.shared.global [%0], [%1], 16;" :: "r"(dst), "l"(src));
}
#define CP_COMMIT() asm volatile("cp.async.commit_group;" ::: "memory")
#define CP_WAIT1()  asm volatile("cp.async.wait_group 1;" ::: "memory")
#define CP_WAIT0()  asm volatile("cp.async.wait_group 0;" ::: "memory")

// ============================================================
// K0: pack We [E][A] fp32 -> g_Wp [A][E/2] fp16x2 (k-pairs)
// grid (E/64=32, A/32=16), block (32,8)
// ============================================================
__global__ __launch_bounds__(256) void pack_we(const float* __restrict__ We)
{
    __shared__ float s[64][33];
    const int k0 = blockIdx.x * 64, n0 = blockIdx.y * 32;
    const int tx = threadIdx.x, ty = threadIdx.y;
    #pragma unroll
    for (int j = ty; j < 64; j += 8)
        s[j][tx] = We[(size_t)(k0 + j)*A_ + n0 + tx];
    __syncthreads();
    const int kp0 = blockIdx.x * 32;
    #pragma unroll
    for (int j = ty; j < 32; j += 8)
        g_Wp[(size_t)(n0 + j)*(E_/2) + kp0 + tx] = pack2(s[2*tx][j], s[2*tx+1][j]);
}

// ============================================================
// K1: g_c2[b][a] = dec[b]@Wd[:,a] + bd[a] + be[a]
// ============================================================
__global__ __launch_bounds__(256) void att2_kernel(
    const float* __restrict__ dec, const float* __restrict__ Wd,
    const float* __restrict__ bd,  const float* __restrict__ be)
{
    __shared__ float sDec[16*D_];
    const int tid = threadIdx.x;
    const int a0 = blockIdx.x*128, b0 = blockIdx.y*16;

    const float4* src = (const float4*)(dec + (size_t)b0*D_);
    float4* dst = (float4*)sDec;
    for (int i=tid; i<16*D_/4; i+=256) dst[i] = src[i];
    __syncthreads();

    const int tx = tid & 31, ty = tid >> 5;
    const float4* wp = (const float4*)(Wd + a0) + tx;
    float4 acc0 = {0,0,0,0}, acc1 = {0,0,0,0};
    for (int d=0; d<D_; d++){
        float4 w = wp[(size_t)d*(A_/4)];
        float x0 = sDec[ty*D_ + d];
        float x1 = sDec[(ty+8)*D_ + d];
        acc0.x += w.x*x0; acc0.y += w.y*x0; acc0.z += w.z*x0; acc0.w += w.w*x0;
        acc1.x += w.x*x1; acc1.y += w.y*x1; acc1.z += w.z*x1; acc1.w += w.w*x1;
    }
    const int a = a0 + tx*4;
    float bx = bd[a]   + be[a];
    float by = bd[a+1] + be[a+1];
    float bz = bd[a+2] + be[a+2];
    float bw = bd[a+3] + be[a+3];
    float4 o0 = {acc0.x+bx, acc0.y+by, acc0.z+bz, acc0.w+bw};
    float4 o1 = {acc1.x+bx, acc1.y+by, acc1.z+bz, acc1.w+bw};
    *(float4*)&g_c2[(size_t)(b0+ty  )*A_ + a] = o0;
    *(float4*)&g_c2[(size_t)(b0+ty+8)*A_ + a] = o1;
}

// ============================================================
// K2: fused score GEMM (fp16 m16n8k16 mma.sync), cp.async 3-stage
//   CTA tile 128x128, warps 4m x 2n, warp tile 32x64
//   A fp32 in smem (pack at frag load); B pre-packed fp16x2
//   grid (4 a-chunks, 196 m-tiles), 256 threads, 2 CTAs/SM
// ============================================================
#define MT 128
#define NT 128
#define KC 32               // k-values per chunk
#define ASTR 40             // A row stride in floats (LDS.64 conflict-free)
#define BSTRW 20            // B row stride in words (16 + 4 pad)
#define ASTG (MT*ASTR)      // 5120 floats
#define BSTGW (NT*BSTRW)    // 2560 words
#define STGF (ASTG+BSTGW)   // 7680 4-byte units per stage
#define SMEM_K2 (3*STGF*4)  // 92160 B
#define NCH (E_/KC)         // 64

__global__ __launch_bounds__(256,2) void score_kernel(
    const float* __restrict__ enc, const float* __restrict__ Wf)
{
    extern __shared__ float sm[];
    const uint32_t sbase = smem_u32(sm);

    const int tid  = threadIdx.x;
    const int lane = tid & 31, warp = tid >> 5;
    const int wm = (warp >> 1) * 32;   // warp m offset (0,32,64,96)
    const int wn = (warp & 1) * 64;    // warp n offset (0 or 64)
    const int m0 = blockIdx.y * MT;
    const int a0 = blockIdx.x * NT;

    // cp.async maps
    const int ar = tid >> 3,  ak = (tid & 7) * 4;    // A: rows 0..31 (+32p)
    const int bn = tid >> 1,  bw = (tid & 1) * 8;    // B: n row, word offset
    const float*    gA  = enc  + (size_t)(m0 + ar)*E_ + ak;
    const uint32_t* gBp = g_Wp + (size_t)(a0 + bn)*(E_/2) + bw;
    const uint32_t dA = sbase + (ar*ASTR + ak)*4;
    const uint32_t dB = sbase + (ASTG + bn*BSTRW + bw)*4;

    auto issue = [&](int c){
        const int s = c % 3;
        const uint32_t so = s*STGF*4;
        const float* pa = gA + c*KC;
        #pragma unroll
        for (int p=0;p<4;p++)
            cpasync16(so + dA + p*32*ASTR*4, pa + (size_t)p*32*E_);
        const uint32_t* pb = gBp + c*(KC/2);
        cpasync16(so + dB,      pb);
        cpasync16(so + dB + 16, pb + 4);
        CP_COMMIT();
    };

    float acc[2][8][4];
    #pragma unroll
    for (int i=0;i<2;i++)
        #pragma unroll
        for (int j=0;j<8;j++)
            #pragma unroll
            for (int k=0;k<4;k++) acc[i][j][k] = 0.f;

    issue(0); issue(1);

    const int q = lane >> 2;      // 0..7
    const int c = lane & 3;       // 0..3

    for (int kc=0; kc<NCH; kc++){
        if (kc < NCH-2) { CP_WAIT1(); } else { CP_WAIT0(); }
        __syncthreads();

        const float* cA = sm + (kc%3)*STGF;
        const uint32_t* cBw = (const uint32_t*)(cA + ASTG);
        #pragma unroll
        for (int kk=0; kk<2; kk++){
            uint32_t af[2][4], bfr[8][2];
            #pragma unroll
            for (int ms=0; ms<2; ms++){
                const float* p = cA + (wm + ms*16 + q)*ASTR + kk*16 + 2*c;
                const float2 x0 = *(const float2*)(p);
                const float2 x1 = *(const float2*)(p + 8*ASTR);
                const float2 x2 = *(const float2*)(p + 8);
                const float2 x3 = *(const float2*)(p + 8*ASTR + 8);
                af[ms][0] = pack2(x0.x, x0.y);
                af[ms][1] = pack2(x1.x, x1.y);
                af[ms][2] = pack2(x2.x, x2.y);
                af[ms][3] = pack2(x3.x, x3.y);
            }
            #pragma unroll
            for (int ns=0; ns<8; ns++){
                const uint32_t* p = cBw + (wn + ns*8 + q)*BSTRW + kk*8 + c;
                bfr[ns][0] = p[0];
                bfr[ns][1] = p[4];
            }
            #pragma unroll
            for (int ms=0; ms<2; ms++)
                #pragma unroll
                for (int ns=0; ns<8; ns++)
                    mma16(acc[ms][ns][0],acc[ms][ns][1],acc[ms][ns][2],acc[ms][ns][3],
                          af[ms][0],af[ms][1],af[ms][2],af[ms][3],
                          bfr[ns][0],bfr[ns][1]);
        }
        __syncthreads();
        if (kc < NCH-2) issue(kc+2);
    }

    // ---- epilogue: tanh(+c2) dot Wf, quad-reduce, write partials ----
    const int c2i = c*2;
    #pragma unroll
    for (int ms=0; ms<2; ms++){
        const int r0 = m0 + wm + ms*16 + q;
        const int r1 = r0 + 8;
        const int b0 = r0 / N_;
        const int b1 = r1 / N_;
        float s0 = 0.f, s1 = 0.f;
        #pragma unroll
        for (int ns=0; ns<8; ns++){
            const int ag = a0 + wn + ns*8 + c2i;
            const float w0 = __ldg(&Wf[ag]), w1 = __ldg(&Wf[ag+1]);
            const float c00 = g_c2[(size_t)b0*A_ + ag], c01 = g_c2[(size_t)b0*A_ + ag + 1];
            const float c10 = g_c2[(size_t)b1*A_ + ag], c11 = g_c2[(size_t)b1*A_ + ag + 1];
            s0 += tanhf(acc[ms][ns][0] + c00) * w0 + tanhf(acc[ms][ns][1] + c01) * w1;
            s1 += tanhf(acc[ms][ns][2] + c10) * w0 + tanhf(acc[ms][ns][3] + c11) * w1;
        }
        s0 += __shfl_xor_sync(0xffffffffu, s0, 1);
        s0 += __shfl_xor_sync(0xffffffffu, s0, 2);
        s1 += __shfl_xor_sync(0xffffffffu, s1, 1);
        s1 += __shfl_xor_sync(0xffffffffu, s1, 2);
        if (c == 0){
            g_sp[(size_t)r0*8 + blockIdx.x*2 + (warp & 1)] = s0;
            g_sp[(size_t)r1*8 + blockIdx.x*2 + (warp & 1)] = s1;
        }
    }
}

// ============================================================
// K3: softmax over n per batch (bf offset cancels, dropped)
// ============================================================
__global__ __launch_bounds__(256) void softmax_kernel(float* __restrict__ alpha)
{
    __shared__ float sh[256];
    const int b = blockIdx.x, t = threadIdx.x;
    float val = 0.f;
    if (t < N_){
        const float* p = &g_sp[(size_t)(b*N_ + t)*8];
        #pragma unroll
        for (int j=0;j<8;j++) val += p[j];
    }
    sh[t] = (t < N_) ? val : -1e30f;
    __syncthreads();
    for (int s=128; s>0; s>>=1){
        if (t < s) sh[t] = fmaxf(sh[t], sh[t+s]);
        __syncthreads();
    }
    const float mx = sh[0];
    __syncthreads();
    const float e = (t < N_) ? expf(val - mx) : 0.f;
    sh[t] = e;
    __syncthreads();
    for (int s=128; s>0; s>>=1){
        if (t < s) sh[t] += sh[t+s];
        __syncthreads();
    }
    const float inv = 1.f / sh[0];
    if (t < N_) alpha[(size_t)b*N_ + t] = e * inv;
}

// ============================================================
// K4: context[b][e] = sum_n alpha[b][n]*enc[b][n][e]
// block 512: 4-way n-split + smem combine
// ============================================================
__global__ __launch_bounds__(512) void ctx_kernel(
    const float* __restrict__ enc, const float* __restrict__ alpha,
    float* __restrict__ out)
{
    __shared__ float sal[N_];
    __shared__ float4 sred[3][128];
    const int b = blockIdx.y;
    const int t = threadIdx.x;
    for (int i=t; i<N_; i+=512) sal[i] = alpha[(size_t)b*N_ + i];
    __syncthreads();

    const int col = t & 127;       // float4 column within 512-wide chunk
    const int nq  = t >> 7;        // n-quarter 0..3
    const float4* pe = (const float4*)(enc + (size_t)b*N_*E_ + blockIdx.x*512) + col;
    const int n0 = nq * 49, n1 = n0 + 49;
    float4 acc = {0,0,0,0};
    #pragma unroll 7
    for (int n=n0; n<n1; n++){
        const float a = sal[n];
        const float4 v = pe[(size_t)n*(E_/4)];
        acc.x += v.x*a; acc.y += v.y*a; acc.z += v.z*a; acc.w += v.w*a;
    }
    if (nq > 0) sred[nq-1][col] = acc;
    __syncthreads();
    if (nq == 0){
        #pragma unroll
        for (int j=0;j<3;j++){
            const float4 o = sred[j][col];
            acc.x += o.x; acc.y += o.y; acc.z += o.z; acc.w += o.w;
        }
        ((float4*)(out + (size_t)b*E_ + blockIdx.x*512))[col] = acc;
    }
}

// ============================================================
extern "C" void kernel_launch(void* const* d_in, const int* in_sizes, int n_in,
                              void* d_out, int out_size)
{
    (void)in_sizes; (void)n_in; (void)out_size;
    const float* enc = (const float*)d_in[0];   // (B,N,E)
    const float* dec = (const float*)d_in[1];   // (B,D)
    const float* We  = (const float*)d_in[2];   // (E,A)
    const float* be  = (const float*)d_in[3];   // (A)
    const float* Wd  = (const float*)d_in[4];   // (D,A)
    const float* bd  = (const float*)d_in[5];   // (A)
    const float* Wf  = (const float*)d_in[6];   // (A,1)
    // d_in[7] = bf : softmax-invariant, unused

    float* ctx_out   = (float*)d_out;               // (B,E)
    float* alpha_out = ctx_out + (size_t)B_*E_;     // (B,N,1)

    cudaFuncSetAttribute(score_kernel, cudaFuncAttributeMaxDynamicSharedMemorySize, SMEM_K2);

    pack_we<<<dim3(32,16), dim3(32,8)>>>(We);
    att2_kernel<<<dim3(4,8), 256>>>(dec, Wd, bd, be);
    score_kernel<<<dim3(4,196), 256, SMEM_K2>>>(enc, Wf);
    softmax_kernel<<<128, 256>>>(alpha_out);
    ctx_kernel<<<dim3(4,128), 512>>>(enc, alpha_out, ctx_out);
}